// round 15
// baseline (speedup 1.0000x reference)
#include <cuda_runtime.h>
#include <cstdint>

// Problem constants
#define C_DIM   384
#define N_DIM   1152
#define B_SZ    8
#define H_IMG   224
#define W_IMG   224
#define HWB     50176
#define M_TOT   401408
#define HD      96
#define NHEADS  4

// QKV scratch in fp16 (half2 words): [M_TOT][576 words]; q pre-scaled by 96^-0.5
__device__ uint32_t g_qkvh[(size_t)M_TOT * 576];
// Pre-converted W in fp16 (half2 words): [1152][384] halves
__device__ uint32_t g_wh[221184];

__device__ __forceinline__ uint32_t pack_h2(float lo, float hi) {
    uint32_t r;
    asm("cvt.rn.f16x2.f32 %0, %1, %2;" : "=r"(r) : "f"(hi), "f"(lo));
    return r;   // d<15:0> = lo, d<31:16> = hi
}

__device__ __forceinline__ uint32_t smem_u32(const void* p) {
    uint32_t a;
    asm("{ .reg .u64 t; cvta.to.shared.u64 t, %1; cvt.u32.u64 %0, t; }"
        : "=r"(a) : "l"(p));
    return a;
}

#define CP_ASYNC16(dst, src) \
    asm volatile("cp.async.cg.shared.global [%0], [%1], 16;" \
                 :: "r"(dst), "l"(src) : "memory")
#define CP_COMMIT()  asm volatile("cp.async.commit_group;" ::: "memory")
#define CP_WAIT0()   asm volatile("cp.async.wait_group 0;" ::: "memory")

__device__ __forceinline__ void ldsm_x4(uint32_t& r0, uint32_t& r1,
                                        uint32_t& r2, uint32_t& r3, uint32_t a) {
    asm volatile("ldmatrix.sync.aligned.m8n8.x4.shared.b16 {%0,%1,%2,%3}, [%4];"
                 : "=r"(r0), "=r"(r1), "=r"(r2), "=r"(r3) : "r"(a));
}
__device__ __forceinline__ void ldsm_x4_t(uint32_t& r0, uint32_t& r1,
                                          uint32_t& r2, uint32_t& r3, uint32_t a) {
    asm volatile("ldmatrix.sync.aligned.m8n8.x4.trans.shared.b16 {%0,%1,%2,%3}, [%4];"
                 : "=r"(r0), "=r"(r1), "=r"(r2), "=r"(r3) : "r"(a));
}

__device__ __forceinline__ void mma_f16(float& c0, float& c1, float& c2, float& c3,
                                        uint32_t a0, uint32_t a1, uint32_t a2, uint32_t a3,
                                        uint32_t b0, uint32_t b1) {
    asm volatile(
        "mma.sync.aligned.m16n8k16.row.col.f32.f16.f16.f32 "
        "{%0,%1,%2,%3}, {%4,%5,%6,%7}, {%8,%9}, {%0,%1,%2,%3};"
        : "+f"(c0), "+f"(c1), "+f"(c2), "+f"(c3)
        : "r"(a0), "r"(a1), "r"(a2), "r"(a3), "r"(b0), "r"(b1));
}

// ---------------------------------------------------------------------------
// Kernel 0: one-time W fp32 -> fp16 conversion
// ---------------------------------------------------------------------------
__global__ void __launch_bounds__(256) wconv(const float* __restrict__ w)
{
    int i = blockIdx.x * 256 + threadIdx.x;
    if (i < 110592) {
        float4 v = ((const float4*)w)[i];
        uint2 o;
        o.x = pack_h2(v.x, v.y);
        o.y = pack_h2(v.z, v.w);
        ((uint2*)g_wh)[i] = o;
    }
}

// ---------------------------------------------------------------------------
// Kernel 1: QKV GEMM — SYNCLESS mainloop.
//   A[k][m] fp16 in SMEM, XOR swizzle (R11-verified). B fragments loaded
//   directly from L2-resident g_wh via scalar LDG.32 (mapping identical to
//   the ldsm-produced fragments: b0=word lr, b1=lr+4, +8/kc, +16/stage).
//   One __syncthreads after the A prologue; none in the mainloop.
// ---------------------------------------------------------------------------
#define AS_BYTES 98304                      // 384 * 256
#define QKV_SMEM AS_BYTES

__global__ void __launch_bounds__(256, 2) qkv_mma(
    const float* __restrict__ x,
    const float* __restrict__ bias)
{
    extern __shared__ char smem[];
    const uint32_t abase = smem_u32(smem);

    const int tid = threadIdx.x;
    const int wid = tid >> 5;
    const int lid = tid & 31;
    const int mw  = wid & 1;
    const int nw  = wid >> 1;
    const int lq  = lid >> 2;
    const int lr  = lid & 3;
    const int bit3 = (lid >> 3) & 1;
    const int bit4 = (lid >> 4) & 1;

    const int m0 = blockIdx.x * 128;
    const int b  = m0 / HWB;
    const float* xb = x + (size_t)b * C_DIM * HWB + (m0 - b * HWB);

    // ---- A prologue: As[k][m] fp16, XOR-swizzled chunks (R11-verified) ----
    for (int i = tid; i < 12288; i += 256) {
        int k = i >> 5, m4 = i & 31;
        float4 v = *(const float4*)(xb + (size_t)k * HWB + m4 * 4);
        uint32_t h0 = pack_h2(v.x, v.y);
        uint32_t h1 = pack_h2(v.z, v.w);
        int cl = m4 >> 1;
        uint32_t off = (uint32_t)(k * 256
            + (((cl & 8) | ((cl & 7) ^ (k & 7))) * 16) + (m4 & 1) * 8);
        asm volatile("st.shared.v2.b32 [%0], {%1,%2};"
                     :: "r"(abase + off), "r"(h0), "r"(h1));
    }
    __syncthreads();                       // the ONLY block-wide sync

    // Per-lane A ldmatrix address components
    const uint32_t a_row = (uint32_t)((((lid & 7) + bit4 * 8) * 256) + mw * 128);
    uint32_t coff[4];
    #pragma unroll
    for (int i = 0; i < 4; ++i)
        coff[i] = (uint32_t)((((bit3 + 2 * i) ^ (lid & 7)) & 7) * 16);

    // Per-lane B fragment base pointers (4 j sub-tiles)
    const uint32_t* bp[4];
    #pragma unroll
    for (int j = 0; j < 4; ++j)
        bp[j] = g_wh + (size_t)(nw * 32 + j * 8 + lq) * 192 + lr;

    for (int nt = 0; nt < 9; ++nt) {
        const int n0 = nt * 128;
        float c[4][4][4];
        #pragma unroll
        for (int i = 0; i < 4; ++i)
            #pragma unroll
            for (int j = 0; j < 4; ++j)
                c[i][j][0] = c[i][j][1] = c[i][j][2] = c[i][j][3] = 0.f;

        for (int s = 0; s < 12; ++s) {
            // ---- B fragments straight from gmem (L2-resident) ----
            uint32_t breg[4][4];               // [j][kc0.b0, kc0.b1, kc1.b0, kc1.b1]
            const int so = s * 16;
            #pragma unroll
            for (int j = 0; j < 4; ++j) {
                breg[j][0] = bp[j][so + 0];
                breg[j][1] = bp[j][so + 4];
                breg[j][2] = bp[j][so + 8];
                breg[j][3] = bp[j][so + 12];
            }

            // ---- A fragments via ldsm (both k-chunks) ----
            uint32_t a[2][4][4];
            #pragma unroll
            for (int kc = 0; kc < 2; ++kc) {
                const uint32_t sA = abase + (uint32_t)(s * 8192 + kc * 4096) + a_row;
                #pragma unroll
                for (int i = 0; i < 4; ++i)
                    ldsm_x4_t(a[kc][i][0], a[kc][i][1], a[kc][i][2], a[kc][i][3],
                              sA + coff[i]);
            }

            // ---- 32 MMAs ----
            #pragma unroll
            for (int kc = 0; kc < 2; ++kc)
                #pragma unroll
                for (int i = 0; i < 4; ++i)
                    #pragma unroll
                    for (int j = 0; j < 4; ++j)
                        mma_f16(c[i][j][0], c[i][j][1], c[i][j][2], c[i][j][3],
                                a[kc][i][0], a[kc][i][1], a[kc][i][2], a[kc][i][3],
                                breg[j][kc * 2], breg[j][kc * 2 + 1]);
        }

        // ---- Epilogue: bias + q-scale, pack fp16, quad transpose, STG.128 ----
        const float qsc = (n0 < 384) ? 0.10206207261596577f : 1.0f;
        float2 bv[4];
        #pragma unroll
        for (int j = 0; j < 4; ++j)
            bv[j] = *(const float2*)(bias + n0 + nw * 32 + j * 8 + lr * 2);

        const int gcol = (n0 + nw * 32 + lr * 8) >> 1;
        #pragma unroll
        for (int i = 0; i < 4; ++i) {
            uint32_t v0[4], v1[4];
            #pragma unroll
            for (int j = 0; j < 4; ++j) {
                v0[j] = pack_h2((c[i][j][0] + bv[j].x) * qsc,
                                (c[i][j][1] + bv[j].y) * qsc);
                v1[j] = pack_h2((c[i][j][2] + bv[j].x) * qsc,
                                (c[i][j][3] + bv[j].y) * qsc);
            }
            #pragma unroll
            for (int m = 1; m < 4; ++m) {
                v0[lr ^ m] = __shfl_xor_sync(0xffffffffu, v0[lr ^ m], m);
                v1[lr ^ m] = __shfl_xor_sync(0xffffffffu, v1[lr ^ m], m);
            }
            const int gm0 = m0 + mw * 64 + i * 16 + lq;
            *(uint4*)(g_qkvh + (size_t)gm0 * 576 + gcol) =
                make_uint4(v0[0], v0[1], v0[2], v0[3]);
            *(uint4*)(g_qkvh + (size_t)(gm0 + 8) * 576 + gcol) =
                make_uint4(v1[0], v1[1], v1[2], v1[3]);
        }

        // Advance B pointers to next N-tile
        #pragma unroll
        for (int j = 0; j < 4; ++j)
            bp[j] += 128 * 192;
    }
}

// ---------------------------------------------------------------------------
// Kernel 2: tensor-core windowed attention (R14 verbatim)
// ---------------------------------------------------------------------------
#define ROWB 208                      // bytes per Q/K/V row (104 halves)
#define QMB  13312                    // Q: 64 rows
#define KMB  11648                    // K: 56 rows
#define VMB  13312                    // V: 64 rows
#define HSET (QMB + KMB + VMB)        // 38272 per head
#define OST  200                      // osm row stride (floats)
#define AT_SMEM (2 * HSET)            // 76544

__global__ void __launch_bounds__(256, 3) attn_tc(float* __restrict__ out)
{
    extern __shared__ char smem[];
    const int tid  = threadIdx.x;
    const int wgid = tid >> 7;        // head within pair
    const int wrp  = (tid >> 5) & 3;
    const int lid  = tid & 31;
    const int lam  = lid & 3;
    const int win  = blockIdx.x;
    const int hp   = blockIdx.y;      // head pair
    const int b    = win >> 10;
    const int wh   = (win >> 5) & 31;
    const int ww   = win & 31;

    const uint32_t sbase = smem_u32(smem);
    const uint32_t qb = sbase + (uint32_t)(wgid * HSET);
    const uint32_t kb = qb + QMB;
    const uint32_t vb = kb + KMB;
    uint32_t* smw = (uint32_t*)smem;
    float* osm = (float*)smem;        // reused AFTER AV (post-sync)

    // Kick off all Q/K/V loads: 49 tok x 72 chunks (2 heads x 3 segs x 12)
    #pragma unroll
    for (int p = 0; p < 14; ++p) {
        int e = p * 256 + tid;
        if (e < 3528) {
            int tok = e / 72, c = e % 72;
            int seg = c / 24, hl = (c % 24) / 12, f4 = c % 12;
            const uint32_t* src = g_qkvh
                + ((size_t)b * HWB + (wh * 7 + tok / 7) * W_IMG + ww * 7 + tok % 7) * 576
                + seg * 192 + (hp * 2 + hl) * 48 + f4 * 4;
            uint32_t sgo = (seg == 0) ? 0u : ((seg == 1) ? (uint32_t)QMB
                                                         : (uint32_t)(QMB + KMB));
            uint32_t dst = sbase + (uint32_t)(hl * HSET) + sgo
                         + (uint32_t)(tok * ROWB + f4 * 16);
            CP_ASYNC16(dst, (const void*)src);
        }
    }
    CP_COMMIT();

    // Zero pad rows while loads fly: Q 49-63, K 49-55, V 49-63 (both heads)
    for (int i = tid; i < 3848; i += 256) {
        int hl = i / 1924, rem = i % 1924;
        int r37 = rem / 52, w = rem % 52;
        int base, r;
        if (r37 < 15)      { base = 0;    r = 49 + r37; }        // Q
        else if (r37 < 22) { base = 3328; r = 49 + r37 - 15; }   // K (words)
        else               { base = 6240; r = 49 + r37 - 22; }   // V
        smw[hl * (HSET / 4) + base + r * 52 + w] = 0u;
    }
    CP_WAIT0();
    __syncthreads();

    // ---- Scores: S[q][key] = Q . K (per warpgroup = per head) ----
    const int q0 = wrp * 16;
    const uint32_t a_addr = qb + (uint32_t)((q0 + (lid & 15)) * ROWB + (lid >> 4) * 16);
    const uint32_t k_rsel = (uint32_t)((((lid >> 4) & 1) * 8 + (lid & 7)) * ROWB
                                       + ((lid >> 3) & 1) * 16);
    float sc[7][4];
    #pragma unroll
    for (int t = 0; t < 7; ++t)
        sc[t][0] = sc[t][1] = sc[t][2] = sc[t][3] = 0.f;

    #pragma unroll
    for (int s = 0; s < 6; ++s) {
        uint32_t a0, a1, a2, a3;
        ldsm_x4(a0, a1, a2, a3, a_addr + (uint32_t)(s * 32));
        #pragma unroll
        for (int np = 0; np < 4; ++np) {
            uint32_t r0, r1, r2, r3;
            ldsm_x4(r0, r1, r2, r3, kb + k_rsel + (uint32_t)(np * 16 * ROWB + s * 32));
            mma_f16(sc[2*np][0], sc[2*np][1], sc[2*np][2], sc[2*np][3],
                    a0, a1, a2, a3, r0, r1);
            if (np < 3)
                mma_f16(sc[2*np+1][0], sc[2*np+1][1], sc[2*np+1][2], sc[2*np+1][3],
                        a0, a1, a2, a3, r2, r3);
        }
    }

    // ---- Softmax in registers; pack probs to fp16 immediately ----
    float mx0 = -1e30f, mx1 = -1e30f;
    #pragma unroll
    for (int t = 0; t < 6; ++t) {
        mx0 = fmaxf(mx0, fmaxf(sc[t][0], sc[t][1]));
        mx1 = fmaxf(mx1, fmaxf(sc[t][2], sc[t][3]));
    }
    if (lam == 0) { mx0 = fmaxf(mx0, sc[6][0]); mx1 = fmaxf(mx1, sc[6][2]); }
    mx0 = fmaxf(mx0, __shfl_xor_sync(0xffffffffu, mx0, 1));
    mx0 = fmaxf(mx0, __shfl_xor_sync(0xffffffffu, mx0, 2));
    mx1 = fmaxf(mx1, __shfl_xor_sync(0xffffffffu, mx1, 1));
    mx1 = fmaxf(mx1, __shfl_xor_sync(0xffffffffu, mx1, 2));

    uint32_t ph[7][2];
    float sum0 = 0.f, sum1 = 0.f;
    #pragma unroll
    for (int t = 0; t < 6; ++t) {
        float e0 = __expf(sc[t][0] - mx0);
        float e1 = __expf(sc[t][1] - mx0);
        float e2 = __expf(sc[t][2] - mx1);
        float e3 = __expf(sc[t][3] - mx1);
        sum0 += e0 + e1;
        sum1 += e2 + e3;
        ph[t][0] = pack_h2(e0, e1);
        ph[t][1] = pack_h2(e2, e3);
    }
    {
        float e0 = (lam == 0) ? __expf(sc[6][0] - mx0) : 0.f;
        float e2 = (lam == 0) ? __expf(sc[6][2] - mx1) : 0.f;
        sum0 += e0;
        sum1 += e2;
        ph[6][0] = pack_h2(e0, 0.f);
        ph[6][1] = pack_h2(e2, 0.f);
    }
    sum0 += __shfl_xor_sync(0xffffffffu, sum0, 1);
    sum0 += __shfl_xor_sync(0xffffffffu, sum0, 2);
    sum1 += __shfl_xor_sync(0xffffffffu, sum1, 1);
    sum1 += __shfl_xor_sync(0xffffffffu, sum1, 2);
    const float inv0 = 1.f / sum0;
    const float inv1 = 1.f / sum1;

    // ---- AV: out = P . V (normalize after) ----
    float co[12][4];
    #pragma unroll
    for (int t = 0; t < 12; ++t)
        co[t][0] = co[t][1] = co[t][2] = co[t][3] = 0.f;

    const uint32_t v_rsel = (uint32_t)((lid & 15) * ROWB + ((lid >> 4) & 1) * 16);
    #pragma unroll
    for (int t = 0; t < 4; ++t) {
        uint32_t a0 = ph[2*t][0];
        uint32_t a1 = ph[2*t][1];
        uint32_t a2 = (t < 3) ? ph[2*t+1][0] : 0u;
        uint32_t a3 = (t < 3) ? ph[2*t+1][1] : 0u;
        #pragma unroll
        for (int np = 0; np < 6; ++np) {
            uint32_t r0, r1, r2, r3;
            ldsm_x4_t(r0, r1, r2, r3, vb + v_rsel + (uint32_t)(t * 16 * ROWB + np * 32));
            mma_f16(co[2*np][0], co[2*np][1], co[2*np][2], co[2*np][3],
                    a0, a1, a2, a3, r0, r1);
            mma_f16(co[2*np+1][0], co[2*np+1][1], co[2*np+1][2], co[2*np+1][3],
                    a0, a1, a2, a3, r2, r3);
        }
    }
    __syncthreads();   // both heads done with Q/K/V smem -> reuse as osm

    // ---- Stage normalized output rows to osm[49][2*96] (stride 200) ----
    {
        const int r   = lid >> 2;
        const int rg0 = q0 + r;
        const int rg8 = q0 + r + 8;
        const int dh  = wgid * 96;
        #pragma unroll
        for (int nt = 0; nt < 12; ++nt) {
            const int d = dh + nt * 8 + 2 * lam;
            if (rg0 < 49)
                *(float2*)(osm + rg0 * OST + d) =
                    make_float2(co[nt][0] * inv0, co[nt][1] * inv0);
            if (rg8 < 49)
                *(float2*)(osm + rg8 * OST + d) =
                    make_float2(co[nt][2] * inv1, co[nt][3] * inv1);
        }
    }
    __syncthreads();

    // ---- Coalesced-ish global write (w-contiguous runs of 7) ----
    for (int e = tid; e < 9408; e += 256) {
        int tok = e % 49, d = e / 49;                 // d in 0..191
        out[(((size_t)b * C_DIM + hp * 192 + d) * H_IMG + wh * 7 + tok / 7) * W_IMG
            + ww * 7 + tok % 7] = osm[tok * OST + d];
    }
}

// ---------------------------------------------------------------------------
extern "C" void kernel_launch(void* const* d_in, const int* in_sizes, int n_in,
                              void* d_out, int out_size)
{
    const float* x    = (const float*)d_in[0];
    const float* w    = (const float*)d_in[1];
    const float* bias = (const float*)d_in[2];
    float* out        = (float*)d_out;

    cudaFuncSetAttribute(qkv_mma, cudaFuncAttributeMaxDynamicSharedMemorySize,
                         (int)QKV_SMEM);
    cudaFuncSetAttribute(attn_tc, cudaFuncAttributeMaxDynamicSharedMemorySize,
                         (int)AT_SMEM);

    wconv<<<432, 256>>>(w);
    qkv_mma<<<M_TOT / 128, 256, QKV_SMEM>>>(x, bias);
    attn_tc<<<dim3(B_SZ * 32 * 32, 2), 256, AT_SMEM>>>(out);
}

// round 16
// speedup vs baseline: 1.0933x; 1.0933x over previous
#include <cuda_runtime.h>
#include <cstdint>

// Problem constants
#define C_DIM   384
#define N_DIM   1152
#define B_SZ    8
#define H_IMG   224
#define W_IMG   224
#define HWB     50176
#define M_TOT   401408
#define HD      96
#define NHEADS  4

// QKV scratch in fp16 (half2 words): [M_TOT][576 words]; q pre-scaled by 96^-0.5
__device__ uint32_t g_qkvh[(size_t)M_TOT * 576];
// Pre-converted W in fp16 (half2 words): [1152][384] halves
__device__ uint32_t g_wh[221184];

__device__ __forceinline__ uint32_t pack_h2(float lo, float hi) {
    uint32_t r;
    asm("cvt.rn.f16x2.f32 %0, %1, %2;" : "=r"(r) : "f"(hi), "f"(lo));
    return r;   // d<15:0> = lo, d<31:16> = hi
}

__device__ __forceinline__ uint32_t smem_u32(const void* p) {
    uint32_t a;
    asm("{ .reg .u64 t; cvta.to.shared.u64 t, %1; cvt.u32.u64 %0, t; }"
        : "=r"(a) : "l"(p));
    return a;
}

#define CP_ASYNC16(dst, src) \
    asm volatile("cp.async.cg.shared.global [%0], [%1], 16;" \
                 :: "r"(dst), "l"(src) : "memory")
#define CP_COMMIT()  asm volatile("cp.async.commit_group;" ::: "memory")
#define CP_WAIT0()   asm volatile("cp.async.wait_group 0;" ::: "memory")

__device__ __forceinline__ void ldsm_x4(uint32_t& r0, uint32_t& r1,
                                        uint32_t& r2, uint32_t& r3, uint32_t a) {
    asm volatile("ldmatrix.sync.aligned.m8n8.x4.shared.b16 {%0,%1,%2,%3}, [%4];"
                 : "=r"(r0), "=r"(r1), "=r"(r2), "=r"(r3) : "r"(a));
}
__device__ __forceinline__ void ldsm_x4_t(uint32_t& r0, uint32_t& r1,
                                          uint32_t& r2, uint32_t& r3, uint32_t a) {
    asm volatile("ldmatrix.sync.aligned.m8n8.x4.trans.shared.b16 {%0,%1,%2,%3}, [%4];"
                 : "=r"(r0), "=r"(r1), "=r"(r2), "=r"(r3) : "r"(a));
}

__device__ __forceinline__ void mma_f16(float& c0, float& c1, float& c2, float& c3,
                                        uint32_t a0, uint32_t a1, uint32_t a2, uint32_t a3,
                                        uint32_t b0, uint32_t b1) {
    asm volatile(
        "mma.sync.aligned.m16n8k16.row.col.f32.f16.f16.f32 "
        "{%0,%1,%2,%3}, {%4,%5,%6,%7}, {%8,%9}, {%0,%1,%2,%3};"
        : "+f"(c0), "+f"(c1), "+f"(c2), "+f"(c3)
        : "r"(a0), "r"(a1), "r"(a2), "r"(a3), "r"(b0), "r"(b1));
}

// ---------------------------------------------------------------------------
// Kernel 0: one-time W fp32 -> fp16 conversion
// ---------------------------------------------------------------------------
__global__ void __launch_bounds__(256) wconv(const float* __restrict__ w)
{
    int i = blockIdx.x * 256 + threadIdx.x;
    if (i < 110592) {
        float4 v = ((const float4*)w)[i];
        uint2 o;
        o.x = pack_h2(v.x, v.y);
        o.y = pack_h2(v.z, v.w);
        ((uint2*)g_wh)[i] = o;
    }
}

// ---------------------------------------------------------------------------
// Kernel 1: QKV GEMM — M=64 tiles, 3 CTAs/SM, double-buffered cp.async B.
//   A[k][m] fp16, 128B rows, XOR swizzle: phys_chunk = c ^ (k&7).
//   B[n][k] fp16, 64B rows, XOR swizzle (R13-verified).
//   12 stages (32 k) per N-tile; prefetch g+1 while computing g; 1 sync/stage.
// ---------------------------------------------------------------------------
#define AS_BYTES 49152                      // 384 * 128
#define BSTG     8192                       // 128 rows * 64B
#define QKV_SMEM (AS_BYTES + 2 * BSTG)      // 65,536 -> 3 CTAs/SM

__global__ void __launch_bounds__(256, 3) qkv_mma(
    const float* __restrict__ x,
    const float* __restrict__ bias)
{
    extern __shared__ char smem[];
    const uint32_t abase = smem_u32(smem);
    const uint32_t bbase = abase + AS_BYTES;

    const int tid = threadIdx.x;
    const int wid = tid >> 5;
    const int lid = tid & 31;
    const int mw  = wid & 1;             // 2 m-strips of 32 tokens
    const int nw  = wid >> 1;            // 4 n-strips of 32
    const int lq  = lid >> 2;
    const int lr  = lid & 3;
    const int bit3 = (lid >> 3) & 1;
    const int bit4 = (lid >> 4) & 1;

    const int m0 = blockIdx.x * 64;      // 50176 % 64 == 0
    const int b  = m0 / HWB;
    const float* xb = x + (size_t)b * C_DIM * HWB + (m0 - b * HWB);

    // B-stage cp.async mapping (R13-verified): row = tid>>1, 2 chunks
    const int bs_row = tid >> 1;
    const int bs_c0  = (tid & 1) * 2;
    const uint32_t phys0 = (uint32_t)(((bs_c0 ^ ((bs_row >> 1) & 3)) & 3) * 16);
    const uint32_t bs_d0 = bbase + (uint32_t)(bs_row * 64) + phys0;
    const uint32_t bs_d1 = bs_d0 ^ 16u;
    const uint32_t* bs_srcb = g_wh + (size_t)bs_row * 192 + bs_c0 * 4;

    // ---- Preload stage (nt=0, s=0) into buf 0 ----
    CP_ASYNC16(bs_d0, (const void*)bs_srcb);
    CP_ASYNC16(bs_d1, (const void*)(bs_srcb + 4));
    CP_COMMIT();

    // ---- A prologue: As[k][m] fp16, 128B rows, XOR swizzle c ^ (k&7) ----
    // 384 k-rows x 16 m-quads = 6144 float4 loads
    for (int i = tid; i < 6144; i += 256) {
        int k = i >> 4, m4 = i & 15;
        float4 v = *(const float4*)(xb + (size_t)k * HWB + m4 * 4);
        uint32_t h0 = pack_h2(v.x, v.y);
        uint32_t h1 = pack_h2(v.z, v.w);
        uint32_t off = (uint32_t)(k * 128
            + ((((m4 >> 1) ^ (k & 7)) & 7) * 16) + (m4 & 1) * 8);
        asm volatile("st.shared.v2.b32 [%0], {%1,%2};"
                     :: "r"(abase + off), "r"(h0), "r"(h1));
    }
    CP_WAIT0();
    __syncthreads();

    // Per-lane ldmatrix address components
    // A (.trans): row = (lid&7) + bit4*8 within k-chunk; 128B row stride
    const uint32_t a_row = (uint32_t)(((lid & 7) + bit4 * 8) * 128);
    uint32_t coff[2];
    #pragma unroll
    for (int i = 0; i < 2; ++i)
        coff[i] = (uint32_t)((((mw * 4 + i * 2 + bit3) ^ (lid & 7)) & 7) * 16);

    // B (non-trans): 64B rows, XOR swizzle (R13-verified)
    const int  b_row   = nw * 32 + bit4 * 8 + (lid & 7);
    const uint32_t b_roff = (uint32_t)(b_row * 64);
    const uint32_t swzn   = (uint32_t)((b_row >> 1) & 3);
    uint32_t bpc[2];
    bpc[0] = (uint32_t)((((0u + bit3) ^ swzn) & 3u) * 16u);
    bpc[1] = (uint32_t)((((2u + bit3) ^ swzn) & 3u) * 16u);

    for (int nt = 0; nt < 9; ++nt) {
        const int n0 = nt * 128;
        float c[2][4][4];
        #pragma unroll
        for (int i = 0; i < 2; ++i)
            #pragma unroll
            for (int j = 0; j < 4; ++j)
                c[i][j][0] = c[i][j][1] = c[i][j][2] = c[i][j][3] = 0.f;

        for (int s = 0; s < 12; ++s) {
            const int g = nt * 12 + s;           // global stage id
            const bool pf = (g < 107);

            // ---- Prefetch stage g+1 into the other buffer ----
            if (pf) {
                const int gn  = g + 1;
                const int pn0 = (gn / 12) * 128;
                const int ps  = gn - (gn / 12) * 12;
                const uint32_t dbuf = (uint32_t)((gn & 1) * BSTG);
                const uint32_t* src = bs_srcb + (size_t)pn0 * 192 + ps * 16;
                CP_ASYNC16(bs_d0 + dbuf, (const void*)src);
                CP_ASYNC16(bs_d1 + dbuf, (const void*)(src + 4));
                CP_COMMIT();
            }

            // ---- Compute stage s from buf (g & 1) ----
            const uint32_t bufb = bbase + (uint32_t)((g & 1) * BSTG);
            #pragma unroll
            for (int kc = 0; kc < 2; ++kc) {
                uint32_t a[2][4], bb[2][4];
                const uint32_t sA = abase + (uint32_t)(s * 4096 + kc * 2048) + a_row;
                #pragma unroll
                for (int i = 0; i < 2; ++i)
                    ldsm_x4_t(a[i][0], a[i][1], a[i][2], a[i][3], sA + coff[i]);
                const uint32_t sB = bufb + b_roff + bpc[kc];
                #pragma unroll
                for (int jp = 0; jp < 2; ++jp)
                    ldsm_x4(bb[jp][0], bb[jp][1], bb[jp][2], bb[jp][3],
                            sB + (uint32_t)(jp * 1024));
                #pragma unroll
                for (int i = 0; i < 2; ++i)
                    #pragma unroll
                    for (int j = 0; j < 4; ++j) {
                        const int jp = j >> 1, lo = (j & 1) * 2;
                        mma_f16(c[i][j][0], c[i][j][1], c[i][j][2], c[i][j][3],
                                a[i][0], a[i][1], a[i][2], a[i][3],
                                bb[jp][lo], bb[jp][lo + 1]);
                    }
            }

            if (pf) CP_WAIT0();
            __syncthreads();
        }

        // ---- Epilogue: bias + q-scale, pack fp16, quad transpose, STG.128 ----
        const float qsc = (n0 < 384) ? 0.10206207261596577f : 1.0f;
        float2 bv[4];
        #pragma unroll
        for (int j = 0; j < 4; ++j)
            bv[j] = *(const float2*)(bias + n0 + nw * 32 + j * 8 + lr * 2);

        const int gcol = (n0 + nw * 32 + lr * 8) >> 1;
        #pragma unroll
        for (int i = 0; i < 2; ++i) {
            uint32_t v0[4], v1[4];
            #pragma unroll
            for (int j = 0; j < 4; ++j) {
                v0[j] = pack_h2((c[i][j][0] + bv[j].x) * qsc,
                                (c[i][j][1] + bv[j].y) * qsc);
                v1[j] = pack_h2((c[i][j][2] + bv[j].x) * qsc,
                                (c[i][j][3] + bv[j].y) * qsc);
            }
            #pragma unroll
            for (int m = 1; m < 4; ++m) {
                v0[lr ^ m] = __shfl_xor_sync(0xffffffffu, v0[lr ^ m], m);
                v1[lr ^ m] = __shfl_xor_sync(0xffffffffu, v1[lr ^ m], m);
            }
            const int gm0 = m0 + mw * 32 + i * 16 + lq;
            *(uint4*)(g_qkvh + (size_t)gm0 * 576 + gcol) =
                make_uint4(v0[0], v0[1], v0[2], v0[3]);
            *(uint4*)(g_qkvh + (size_t)(gm0 + 8) * 576 + gcol) =
                make_uint4(v1[0], v1[1], v1[2], v1[3]);
        }
    }
}

// ---------------------------------------------------------------------------
// Kernel 2: tensor-core windowed attention (R14 verbatim — best known)
// ---------------------------------------------------------------------------
#define ROWB 208                      // bytes per Q/K/V row (104 halves)
#define QMB  13312                    // Q: 64 rows
#define KMB  11648                    // K: 56 rows
#define VMB  13312                    // V: 64 rows
#define HSET (QMB + KMB + VMB)        // 38272 per head
#define OST  200                      // osm row stride (floats)
#define AT_SMEM (2 * HSET)            // 76544

__global__ void __launch_bounds__(256, 3) attn_tc(float* __restrict__ out)
{
    extern __shared__ char smem[];
    const int tid  = threadIdx.x;
    const int wgid = tid >> 7;        // head within pair
    const int wrp  = (tid >> 5) & 3;
    const int lid  = tid & 31;
    const int lam  = lid & 3;
    const int win  = blockIdx.x;
    const int hp   = blockIdx.y;      // head pair
    const int b    = win >> 10;
    const int wh   = (win >> 5) & 31;
    const int ww   = win & 31;

    const uint32_t sbase = smem_u32(smem);
    const uint32_t qb = sbase + (uint32_t)(wgid * HSET);
    const uint32_t kb = qb + QMB;
    const uint32_t vb = kb + KMB;
    uint32_t* smw = (uint32_t*)smem;
    float* osm = (float*)smem;        // reused AFTER AV (post-sync)

    // Kick off all Q/K/V loads: 49 tok x 72 chunks (2 heads x 3 segs x 12)
    #pragma unroll
    for (int p = 0; p < 14; ++p) {
        int e = p * 256 + tid;
        if (e < 3528) {
            int tok = e / 72, c = e % 72;
            int seg = c / 24, hl = (c % 24) / 12, f4 = c % 12;
            const uint32_t* src = g_qkvh
                + ((size_t)b * HWB + (wh * 7 + tok / 7) * W_IMG + ww * 7 + tok % 7) * 576
                + seg * 192 + (hp * 2 + hl) * 48 + f4 * 4;
            uint32_t sgo = (seg == 0) ? 0u : ((seg == 1) ? (uint32_t)QMB
                                                         : (uint32_t)(QMB + KMB));
            uint32_t dst = sbase + (uint32_t)(hl * HSET) + sgo
                         + (uint32_t)(tok * ROWB + f4 * 16);
            CP_ASYNC16(dst, (const void*)src);
        }
    }
    CP_COMMIT();

    // Zero pad rows while loads fly: Q 49-63, K 49-55, V 49-63 (both heads)
    for (int i = tid; i < 3848; i += 256) {
        int hl = i / 1924, rem = i % 1924;
        int r37 = rem / 52, w = rem % 52;
        int base, r;
        if (r37 < 15)      { base = 0;    r = 49 + r37; }        // Q
        else if (r37 < 22) { base = 3328; r = 49 + r37 - 15; }   // K (words)
        else               { base = 6240; r = 49 + r37 - 22; }   // V
        smw[hl * (HSET / 4) + base + r * 52 + w] = 0u;
    }
    CP_WAIT0();
    __syncthreads();

    // ---- Scores: S[q][key] = Q . K (per warpgroup = per head) ----
    const int q0 = wrp * 16;
    const uint32_t a_addr = qb + (uint32_t)((q0 + (lid & 15)) * ROWB + (lid >> 4) * 16);
    const uint32_t k_rsel = (uint32_t)((((lid >> 4) & 1) * 8 + (lid & 7)) * ROWB
                                       + ((lid >> 3) & 1) * 16);
    float sc[7][4];
    #pragma unroll
    for (int t = 0; t < 7; ++t)
        sc[t][0] = sc[t][1] = sc[t][2] = sc[t][3] = 0.f;

    #pragma unroll
    for (int s = 0; s < 6; ++s) {
        uint32_t a0, a1, a2, a3;
        ldsm_x4(a0, a1, a2, a3, a_addr + (uint32_t)(s * 32));
        #pragma unroll
        for (int np = 0; np < 4; ++np) {
            uint32_t r0, r1, r2, r3;
            ldsm_x4(r0, r1, r2, r3, kb + k_rsel + (uint32_t)(np * 16 * ROWB + s * 32));
            mma_f16(sc[2*np][0], sc[2*np][1], sc[2*np][2], sc[2*np][3],
                    a0, a1, a2, a3, r0, r1);
            if (np < 3)
                mma_f16(sc[2*np+1][0], sc[2*np+1][1], sc[2*np+1][2], sc[2*np+1][3],
                        a0, a1, a2, a3, r2, r3);
        }
    }

    // ---- Softmax in registers; pack probs to fp16 immediately ----
    float mx0 = -1e30f, mx1 = -1e30f;
    #pragma unroll
    for (int t = 0; t < 6; ++t) {
        mx0 = fmaxf(mx0, fmaxf(sc[t][0], sc[t][1]));
        mx1 = fmaxf(mx1, fmaxf(sc[t][2], sc[t][3]));
    }
    if (lam == 0) { mx0 = fmaxf(mx0, sc[6][0]); mx1 = fmaxf(mx1, sc[6][2]); }
    mx0 = fmaxf(mx0, __shfl_xor_sync(0xffffffffu, mx0, 1));
    mx0 = fmaxf(mx0, __shfl_xor_sync(0xffffffffu, mx0, 2));
    mx1 = fmaxf(mx1, __shfl_xor_sync(0xffffffffu, mx1, 1));
    mx1 = fmaxf(mx1, __shfl_xor_sync(0xffffffffu, mx1, 2));

    uint32_t ph[7][2];
    float sum0 = 0.f, sum1 = 0.f;
    #pragma unroll
    for (int t = 0; t < 6; ++t) {
        float e0 = __expf(sc[t][0] - mx0);
        float e1 = __expf(sc[t][1] - mx0);
        float e2 = __expf(sc[t][2] - mx1);
        float e3 = __expf(sc[t][3] - mx1);
        sum0 += e0 + e1;
        sum1 += e2 + e3;
        ph[t][0] = pack_h2(e0, e1);
        ph[t][1] = pack_h2(e2, e3);
    }
    {
        float e0 = (lam == 0) ? __expf(sc[6][0] - mx0) : 0.f;
        float e2 = (lam == 0) ? __expf(sc[6][2] - mx1) : 0.f;
        sum0 += e0;
        sum1 += e2;
        ph[6][0] = pack_h2(e0, 0.f);
        ph[6][1] = pack_h2(e2, 0.f);
    }
    sum0 += __shfl_xor_sync(0xffffffffu, sum0, 1);
    sum0 += __shfl_xor_sync(0xffffffffu, sum0, 2);
    sum1 += __shfl_xor_sync(0xffffffffu, sum1, 1);
    sum1 += __shfl_xor_sync(0xffffffffu, sum1, 2);
    const float inv0 = 1.f / sum0;
    const float inv1 = 1.f / sum1;

    // ---- AV: out = P . V (normalize after) ----
    float co[12][4];
    #pragma unroll
    for (int t = 0; t < 12; ++t)
        co[t][0] = co[t][1] = co[t][2] = co[t][3] = 0.f;

    const uint32_t v_rsel = (uint32_t)((lid & 15) * ROWB + ((lid >> 4) & 1) * 16);
    #pragma unroll
    for (int t = 0; t < 4; ++t) {
        uint32_t a0 = ph[2*t][0];
        uint32_t a1 = ph[2*t][1];
        uint32_t a2 = (t < 3) ? ph[2*t+1][0] : 0u;
        uint32_t a3 = (t < 3) ? ph[2*t+1][1] : 0u;
        #pragma unroll
        for (int np = 0; np < 6; ++np) {
            uint32_t r0, r1, r2, r3;
            ldsm_x4_t(r0, r1, r2, r3, vb + v_rsel + (uint32_t)(t * 16 * ROWB + np * 32));
            mma_f16(co[2*np][0], co[2*np][1], co[2*np][2], co[2*np][3],
                    a0, a1, a2, a3, r0, r1);
            mma_f16(co[2*np+1][0], co[2*np+1][1], co[2*np+1][2], co[2*np+1][3],
                    a0, a1, a2, a3, r2, r3);
        }
    }
    __syncthreads();   // both heads done with Q/K/V smem -> reuse as osm

    // ---- Stage normalized output rows to osm[49][2*96] (stride 200) ----
    {
        const int r   = lid >> 2;
        const int rg0 = q0 + r;
        const int rg8 = q0 + r + 8;
        const int dh  = wgid * 96;
        #pragma unroll
        for (int nt = 0; nt < 12; ++nt) {
            const int d = dh + nt * 8 + 2 * lam;
            if (rg0 < 49)
                *(float2*)(osm + rg0 * OST + d) =
                    make_float2(co[nt][0] * inv0, co[nt][1] * inv0);
            if (rg8 < 49)
                *(float2*)(osm + rg8 * OST + d) =
                    make_float2(co[nt][2] * inv1, co[nt][3] * inv1);
        }
    }
    __syncthreads();

    // ---- Coalesced-ish global write (w-contiguous runs of 7) ----
    for (int e = tid; e < 9408; e += 256) {
        int tok = e % 49, d = e / 49;                 // d in 0..191
        out[(((size_t)b * C_DIM + hp * 192 + d) * H_IMG + wh * 7 + tok / 7) * W_IMG
            + ww * 7 + tok % 7] = osm[tok * OST + d];
    }
}

// ---------------------------------------------------------------------------
extern "C" void kernel_launch(void* const* d_in, const int* in_sizes, int n_in,
                              void* d_out, int out_size)
{
    const float* x    = (const float*)d_in[0];
    const float* w    = (const float*)d_in[1];
    const float* bias = (const float*)d_in[2];
    float* out        = (float*)d_out;

    cudaFuncSetAttribute(qkv_mma, cudaFuncAttributeMaxDynamicSharedMemorySize,
                         (int)QKV_SMEM);
    cudaFuncSetAttribute(attn_tc, cudaFuncAttributeMaxDynamicSharedMemorySize,
                         (int)AT_SMEM);

    wconv<<<432, 256>>>(w);
    qkv_mma<<<M_TOT / 64, 256, QKV_SMEM>>>(x, bias);
    attn_tc<<<dim3(B_SZ * 32 * 32, 2), 256, AT_SMEM>>>(out);
}

// round 17
// speedup vs baseline: 1.1668x; 1.0672x over previous
#include <cuda_runtime.h>
#include <cstdint>

// Problem constants
#define C_DIM   384
#define N_DIM   1152
#define B_SZ    8
#define H_IMG   224
#define W_IMG   224
#define HWB     50176
#define M_TOT   401408
#define HD      96
#define NHEADS  4

// QKV scratch in fp16 (half2 words): [M_TOT][576 words]; q pre-scaled by 96^-0.5
__device__ uint32_t g_qkvh[(size_t)M_TOT * 576];
// Pre-converted W in fp16 (half2 words): [1152][384] halves
__device__ uint32_t g_wh[221184];

__device__ __forceinline__ uint32_t pack_h2(float lo, float hi) {
    uint32_t r;
    asm("cvt.rn.f16x2.f32 %0, %1, %2;" : "=r"(r) : "f"(hi), "f"(lo));
    return r;   // d<15:0> = lo, d<31:16> = hi
}

__device__ __forceinline__ uint32_t smem_u32(const void* p) {
    uint32_t a;
    asm("{ .reg .u64 t; cvta.to.shared.u64 t, %1; cvt.u32.u64 %0, t; }"
        : "=r"(a) : "l"(p));
    return a;
}

#define CP_ASYNC16(dst, src) \
    asm volatile("cp.async.cg.shared.global [%0], [%1], 16;" \
                 :: "r"(dst), "l"(src) : "memory")
#define CP_COMMIT()  asm volatile("cp.async.commit_group;" ::: "memory")
#define CP_WAIT0()   asm volatile("cp.async.wait_group 0;" ::: "memory")

__device__ __forceinline__ void ldsm_x4(uint32_t& r0, uint32_t& r1,
                                        uint32_t& r2, uint32_t& r3, uint32_t a) {
    asm volatile("ldmatrix.sync.aligned.m8n8.x4.shared.b16 {%0,%1,%2,%3}, [%4];"
                 : "=r"(r0), "=r"(r1), "=r"(r2), "=r"(r3) : "r"(a));
}
__device__ __forceinline__ void ldsm_x4_t(uint32_t& r0, uint32_t& r1,
                                          uint32_t& r2, uint32_t& r3, uint32_t a) {
    asm volatile("ldmatrix.sync.aligned.m8n8.x4.trans.shared.b16 {%0,%1,%2,%3}, [%4];"
                 : "=r"(r0), "=r"(r1), "=r"(r2), "=r"(r3) : "r"(a));
}

__device__ __forceinline__ void mma_f16(float& c0, float& c1, float& c2, float& c3,
                                        uint32_t a0, uint32_t a1, uint32_t a2, uint32_t a3,
                                        uint32_t b0, uint32_t b1) {
    asm volatile(
        "mma.sync.aligned.m16n8k16.row.col.f32.f16.f16.f32 "
        "{%0,%1,%2,%3}, {%4,%5,%6,%7}, {%8,%9}, {%0,%1,%2,%3};"
        : "+f"(c0), "+f"(c1), "+f"(c2), "+f"(c3)
        : "r"(a0), "r"(a1), "r"(a2), "r"(a3), "r"(b0), "r"(b1));
}

// ---------------------------------------------------------------------------
// Kernel 0: one-time W fp32 -> fp16 conversion
// ---------------------------------------------------------------------------
__global__ void __launch_bounds__(256) wconv(const float* __restrict__ w)
{
    int i = blockIdx.x * 256 + threadIdx.x;
    if (i < 110592) {
        float4 v = ((const float4*)w)[i];
        uint2 o;
        o.x = pack_h2(v.x, v.y);
        o.y = pack_h2(v.z, v.w);
        ((uint2*)g_wh)[i] = o;
    }
}

// ---------------------------------------------------------------------------
// Kernel 1: QKV GEMM — M=64 tiles, 3 CTAs/SM (R16 verbatim)
// ---------------------------------------------------------------------------
#define AS_BYTES 49152                      // 384 * 128
#define BSTG     8192                       // 128 rows * 64B
#define QKV_SMEM (AS_BYTES + 2 * BSTG)      // 65,536 -> 3 CTAs/SM

__global__ void __launch_bounds__(256, 3) qkv_mma(
    const float* __restrict__ x,
    const float* __restrict__ bias)
{
    extern __shared__ char smem[];
    const uint32_t abase = smem_u32(smem);
    const uint32_t bbase = abase + AS_BYTES;

    const int tid = threadIdx.x;
    const int wid = tid >> 5;
    const int lid = tid & 31;
    const int mw  = wid & 1;
    const int nw  = wid >> 1;
    const int lq  = lid >> 2;
    const int lr  = lid & 3;
    const int bit3 = (lid >> 3) & 1;
    const int bit4 = (lid >> 4) & 1;

    const int m0 = blockIdx.x * 64;
    const int b  = m0 / HWB;
    const float* xb = x + (size_t)b * C_DIM * HWB + (m0 - b * HWB);

    const int bs_row = tid >> 1;
    const int bs_c0  = (tid & 1) * 2;
    const uint32_t phys0 = (uint32_t)(((bs_c0 ^ ((bs_row >> 1) & 3)) & 3) * 16);
    const uint32_t bs_d0 = bbase + (uint32_t)(bs_row * 64) + phys0;
    const uint32_t bs_d1 = bs_d0 ^ 16u;
    const uint32_t* bs_srcb = g_wh + (size_t)bs_row * 192 + bs_c0 * 4;

    CP_ASYNC16(bs_d0, (const void*)bs_srcb);
    CP_ASYNC16(bs_d1, (const void*)(bs_srcb + 4));
    CP_COMMIT();

    for (int i = tid; i < 6144; i += 256) {
        int k = i >> 4, m4 = i & 15;
        float4 v = *(const float4*)(xb + (size_t)k * HWB + m4 * 4);
        uint32_t h0 = pack_h2(v.x, v.y);
        uint32_t h1 = pack_h2(v.z, v.w);
        uint32_t off = (uint32_t)(k * 128
            + ((((m4 >> 1) ^ (k & 7)) & 7) * 16) + (m4 & 1) * 8);
        asm volatile("st.shared.v2.b32 [%0], {%1,%2};"
                     :: "r"(abase + off), "r"(h0), "r"(h1));
    }
    CP_WAIT0();
    __syncthreads();

    const uint32_t a_row = (uint32_t)(((lid & 7) + bit4 * 8) * 128);
    uint32_t coff[2];
    #pragma unroll
    for (int i = 0; i < 2; ++i)
        coff[i] = (uint32_t)((((mw * 4 + i * 2 + bit3) ^ (lid & 7)) & 7) * 16);

    const int  b_row   = nw * 32 + bit4 * 8 + (lid & 7);
    const uint32_t b_roff = (uint32_t)(b_row * 64);
    const uint32_t swzn   = (uint32_t)((b_row >> 1) & 3);
    uint32_t bpc[2];
    bpc[0] = (uint32_t)((((0u + bit3) ^ swzn) & 3u) * 16u);
    bpc[1] = (uint32_t)((((2u + bit3) ^ swzn) & 3u) * 16u);

    for (int nt = 0; nt < 9; ++nt) {
        const int n0 = nt * 128;
        float c[2][4][4];
        #pragma unroll
        for (int i = 0; i < 2; ++i)
            #pragma unroll
            for (int j = 0; j < 4; ++j)
                c[i][j][0] = c[i][j][1] = c[i][j][2] = c[i][j][3] = 0.f;

        for (int s = 0; s < 12; ++s) {
            const int g = nt * 12 + s;
            const bool pf = (g < 107);

            if (pf) {
                const int gn  = g + 1;
                const int pn0 = (gn / 12) * 128;
                const int ps  = gn - (gn / 12) * 12;
                const uint32_t dbuf = (uint32_t)((gn & 1) * BSTG);
                const uint32_t* src = bs_srcb + (size_t)pn0 * 192 + ps * 16;
                CP_ASYNC16(bs_d0 + dbuf, (const void*)src);
                CP_ASYNC16(bs_d1 + dbuf, (const void*)(src + 4));
                CP_COMMIT();
            }

            const uint32_t bufb = bbase + (uint32_t)((g & 1) * BSTG);
            #pragma unroll
            for (int kc = 0; kc < 2; ++kc) {
                uint32_t a[2][4], bb[2][4];
                const uint32_t sA = abase + (uint32_t)(s * 4096 + kc * 2048) + a_row;
                #pragma unroll
                for (int i = 0; i < 2; ++i)
                    ldsm_x4_t(a[i][0], a[i][1], a[i][2], a[i][3], sA + coff[i]);
                const uint32_t sB = bufb + b_roff + bpc[kc];
                #pragma unroll
                for (int jp = 0; jp < 2; ++jp)
                    ldsm_x4(bb[jp][0], bb[jp][1], bb[jp][2], bb[jp][3],
                            sB + (uint32_t)(jp * 1024));
                #pragma unroll
                for (int i = 0; i < 2; ++i)
                    #pragma unroll
                    for (int j = 0; j < 4; ++j) {
                        const int jp = j >> 1, lo = (j & 1) * 2;
                        mma_f16(c[i][j][0], c[i][j][1], c[i][j][2], c[i][j][3],
                                a[i][0], a[i][1], a[i][2], a[i][3],
                                bb[jp][lo], bb[jp][lo + 1]);
                    }
            }

            if (pf) CP_WAIT0();
            __syncthreads();
        }

        const float qsc = (n0 < 384) ? 0.10206207261596577f : 1.0f;
        float2 bv[4];
        #pragma unroll
        for (int j = 0; j < 4; ++j)
            bv[j] = *(const float2*)(bias + n0 + nw * 32 + j * 8 + lr * 2);

        const int gcol = (n0 + nw * 32 + lr * 8) >> 1;
        #pragma unroll
        for (int i = 0; i < 2; ++i) {
            uint32_t v0[4], v1[4];
            #pragma unroll
            for (int j = 0; j < 4; ++j) {
                v0[j] = pack_h2((c[i][j][0] + bv[j].x) * qsc,
                                (c[i][j][1] + bv[j].y) * qsc);
                v1[j] = pack_h2((c[i][j][2] + bv[j].x) * qsc,
                                (c[i][j][3] + bv[j].y) * qsc);
            }
            #pragma unroll
            for (int m = 1; m < 4; ++m) {
                v0[lr ^ m] = __shfl_xor_sync(0xffffffffu, v0[lr ^ m], m);
                v1[lr ^ m] = __shfl_xor_sync(0xffffffffu, v1[lr ^ m], m);
            }
            const int gm0 = m0 + mw * 32 + i * 16 + lq;
            *(uint4*)(g_qkvh + (size_t)gm0 * 576 + gcol) =
                make_uint4(v0[0], v0[1], v0[2], v0[3]);
            *(uint4*)(g_qkvh + (size_t)(gm0 + 8) * 576 + gcol) =
                make_uint4(v1[0], v1[1], v1[2], v1[3]);
        }
    }
}

// ---------------------------------------------------------------------------
// Kernel 2: tensor-core windowed attention — 2 heads/block, 3 blocks/SM.
//   R14 compute; prologue/epilogue index math strength-reduced (no in-loop
//   divisions; pad-zeroing via contiguous uint4 stores).
// ---------------------------------------------------------------------------
#define ROWB 208                      // bytes per Q/K/V row (104 halves)
#define QMB  13312                    // Q: 64 rows
#define KMB  11648                    // K: 56 rows
#define VMB  13312                    // V: 64 rows
#define HSET (QMB + KMB + VMB)        // 38272 per head
#define OST  200                      // osm row stride (floats)
#define AT_SMEM (2 * HSET)            // 76544

__global__ void __launch_bounds__(256, 3) attn_tc(float* __restrict__ out)
{
    extern __shared__ char smem[];
    const int tid  = threadIdx.x;
    const int wgid = tid >> 7;        // head within pair
    const int wrp  = (tid >> 5) & 3;
    const int lid  = tid & 31;
    const int lam  = lid & 3;
    const int win  = blockIdx.x;
    const int hp   = blockIdx.y;      // head pair
    const int b    = win >> 10;
    const int wh   = (win >> 5) & 31;
    const int ww   = win & 31;

    const uint32_t sbase = smem_u32(smem);
    const uint32_t qb = sbase + (uint32_t)(wgid * HSET);
    const uint32_t kb = qb + QMB;
    const uint32_t vb = kb + KMB;
    float* osm = (float*)smem;        // reused AFTER AV (post-sync)

    // Kick off all Q/K/V loads: 49 tok x 72 chunks (2 heads x 3 segs x 12)
    #pragma unroll
    for (int p = 0; p < 14; ++p) {
        int e = p * 256 + tid;
        if (e < 3528) {
            int tok = e / 72, c = e % 72;
            int seg = c / 24, hl = (c % 24) / 12, f4 = c % 12;
            const uint32_t* src = g_qkvh
                + ((size_t)b * HWB + (wh * 7 + tok / 7) * W_IMG + ww * 7 + tok % 7) * 576
                + seg * 192 + (hp * 2 + hl) * 48 + f4 * 4;
            uint32_t sgo = (seg == 0) ? 0u : ((seg == 1) ? (uint32_t)QMB
                                                         : (uint32_t)(QMB + KMB));
            uint32_t dst = sbase + (uint32_t)(hl * HSET) + sgo
                         + (uint32_t)(tok * ROWB + f4 * 16);
            CP_ASYNC16(dst, (const void*)src);
        }
    }
    CP_COMMIT();

    // Zero pad rows (contiguous per matrix): Q 49-63, K 49-55, V 49-63.
    // uint4 counts per head: Q 195, K 91, V 195 -> 481; both heads 962.
    for (int i = tid; i < 962; i += 256) {
        int hl = (i >= 481);
        int j  = i - hl * 481;
        uint32_t off;
        if (j < 195)      off = 10192u + (uint32_t)j * 16u;            // Q pad
        else if (j < 286) off = 23504u + (uint32_t)(j - 195) * 16u;    // K pad
        else              off = 35152u + (uint32_t)(j - 286) * 16u;    // V pad
        uint32_t dst = sbase + (uint32_t)(hl * HSET) + off;
        asm volatile("st.shared.v4.b32 [%0], {%1,%1,%1,%1};"
                     :: "r"(dst), "r"(0u) : "memory");
    }
    CP_WAIT0();
    __syncthreads();

    // ---- Scores: S[q][key] = Q . K (per warpgroup = per head) ----
    const int q0 = wrp * 16;
    const uint32_t a_addr = qb + (uint32_t)((q0 + (lid & 15)) * ROWB + (lid >> 4) * 16);
    const uint32_t k_rsel = (uint32_t)((((lid >> 4) & 1) * 8 + (lid & 7)) * ROWB
                                       + ((lid >> 3) & 1) * 16);
    float sc[7][4];
    #pragma unroll
    for (int t = 0; t < 7; ++t)
        sc[t][0] = sc[t][1] = sc[t][2] = sc[t][3] = 0.f;

    #pragma unroll
    for (int s = 0; s < 6; ++s) {
        uint32_t a0, a1, a2, a3;
        ldsm_x4(a0, a1, a2, a3, a_addr + (uint32_t)(s * 32));
        #pragma unroll
        for (int np = 0; np < 4; ++np) {
            uint32_t r0, r1, r2, r3;
            ldsm_x4(r0, r1, r2, r3, kb + k_rsel + (uint32_t)(np * 16 * ROWB + s * 32));
            mma_f16(sc[2*np][0], sc[2*np][1], sc[2*np][2], sc[2*np][3],
                    a0, a1, a2, a3, r0, r1);
            if (np < 3)
                mma_f16(sc[2*np+1][0], sc[2*np+1][1], sc[2*np+1][2], sc[2*np+1][3],
                        a0, a1, a2, a3, r2, r3);
        }
    }

    // ---- Softmax in registers; pack probs to fp16 immediately ----
    float mx0 = -1e30f, mx1 = -1e30f;
    #pragma unroll
    for (int t = 0; t < 6; ++t) {
        mx0 = fmaxf(mx0, fmaxf(sc[t][0], sc[t][1]));
        mx1 = fmaxf(mx1, fmaxf(sc[t][2], sc[t][3]));
    }
    if (lam == 0) { mx0 = fmaxf(mx0, sc[6][0]); mx1 = fmaxf(mx1, sc[6][2]); }
    mx0 = fmaxf(mx0, __shfl_xor_sync(0xffffffffu, mx0, 1));
    mx0 = fmaxf(mx0, __shfl_xor_sync(0xffffffffu, mx0, 2));
    mx1 = fmaxf(mx1, __shfl_xor_sync(0xffffffffu, mx1, 1));
    mx1 = fmaxf(mx1, __shfl_xor_sync(0xffffffffu, mx1, 2));

    uint32_t ph[7][2];
    float sum0 = 0.f, sum1 = 0.f;
    #pragma unroll
    for (int t = 0; t < 6; ++t) {
        float e0 = __expf(sc[t][0] - mx0);
        float e1 = __expf(sc[t][1] - mx0);
        float e2 = __expf(sc[t][2] - mx1);
        float e3 = __expf(sc[t][3] - mx1);
        sum0 += e0 + e1;
        sum1 += e2 + e3;
        ph[t][0] = pack_h2(e0, e1);
        ph[t][1] = pack_h2(e2, e3);
    }
    {
        float e0 = (lam == 0) ? __expf(sc[6][0] - mx0) : 0.f;
        float e2 = (lam == 0) ? __expf(sc[6][2] - mx1) : 0.f;
        sum0 += e0;
        sum1 += e2;
        ph[6][0] = pack_h2(e0, 0.f);
        ph[6][1] = pack_h2(e2, 0.f);
    }
    sum0 += __shfl_xor_sync(0xffffffffu, sum0, 1);
    sum0 += __shfl_xor_sync(0xffffffffu, sum0, 2);
    sum1 += __shfl_xor_sync(0xffffffffu, sum1, 1);
    sum1 += __shfl_xor_sync(0xffffffffu, sum1, 2);
    const float inv0 = 1.f / sum0;
    const float inv1 = 1.f / sum1;

    // ---- AV: out = P . V (normalize after) ----
    float co[12][4];
    #pragma unroll
    for (int t = 0; t < 12; ++t)
        co[t][0] = co[t][1] = co[t][2] = co[t][3] = 0.f;

    const uint32_t v_rsel = (uint32_t)((lid & 15) * ROWB + ((lid >> 4) & 1) * 16);
    #pragma unroll
    for (int t = 0; t < 4; ++t) {
        uint32_t a0 = ph[2*t][0];
        uint32_t a1 = ph[2*t][1];
        uint32_t a2 = (t < 3) ? ph[2*t+1][0] : 0u;
        uint32_t a3 = (t < 3) ? ph[2*t+1][1] : 0u;
        #pragma unroll
        for (int np = 0; np < 6; ++np) {
            uint32_t r0, r1, r2, r3;
            ldsm_x4_t(r0, r1, r2, r3, vb + v_rsel + (uint32_t)(t * 16 * ROWB + np * 32));
            mma_f16(co[2*np][0], co[2*np][1], co[2*np][2], co[2*np][3],
                    a0, a1, a2, a3, r0, r1);
            mma_f16(co[2*np+1][0], co[2*np+1][1], co[2*np+1][2], co[2*np+1][3],
                    a0, a1, a2, a3, r2, r3);
        }
    }
    __syncthreads();   // both heads done with Q/K/V smem -> reuse as osm

    // ---- Stage normalized output rows to osm[49][2*96] (stride 200) ----
    {
        const int r   = lid >> 2;
        const int rg0 = q0 + r;
        const int rg8 = q0 + r + 8;
        const int dh  = wgid * 96;
        #pragma unroll
        for (int nt = 0; nt < 12; ++nt) {
            const int d = dh + nt * 8 + 2 * lam;
            if (rg0 < 49)
                *(float2*)(osm + rg0 * OST + d) =
                    make_float2(co[nt][0] * inv0, co[nt][1] * inv0);
            if (rg8 < 49)
                *(float2*)(osm + rg8 * OST + d) =
                    make_float2(co[nt][2] * inv1, co[nt][3] * inv1);
        }
    }
    __syncthreads();

    // ---- Global write: strength-reduced (tok,d) walk; no in-loop divisions.
    // e = d*49 + tok, e += 256 per step -> d += 5, tok += 11 (with 49-wrap).
    {
        int tok = tid % 49;
        int d   = tid / 49;
        int th  = tok / 7;
        int tw  = tok - th * 7;
        float* obase = out + (((size_t)b * C_DIM + hp * 192) * H_IMG + wh * 7)
                           * W_IMG + ww * 7;
        while (d < 192) {
            obase[(size_t)d * HWB + th * W_IMG + tw] = osm[tok * OST + d];
            d += 5;
            tok += 11; ++th; tw += 4;
            if (tw >= 7) { tw -= 7; ++th; }
            if (tok >= 49) { tok -= 49; th -= 7; ++d; }
        }
    }
}

// ---------------------------------------------------------------------------
extern "C" void kernel_launch(void* const* d_in, const int* in_sizes, int n_in,
                              void* d_out, int out_size)
{
    const float* x    = (const float*)d_in[0];
    const float* w    = (const float*)d_in[1];
    const float* bias = (const float*)d_in[2];
    float* out        = (float*)d_out;

    cudaFuncSetAttribute(qkv_mma, cudaFuncAttributeMaxDynamicSharedMemorySize,
                         (int)QKV_SMEM);
    cudaFuncSetAttribute(attn_tc, cudaFuncAttributeMaxDynamicSharedMemorySize,
                         (int)AT_SMEM);

    wconv<<<432, 256>>>(w);
    qkv_mma<<<M_TOT / 64, 256, QKV_SMEM>>>(x, bias);
    attn_tc<<<dim3(B_SZ * 32 * 32, 2), 256, AT_SMEM>>>(out);
}